// round 17
// baseline (speedup 1.0000x reference)
#include <cuda_runtime.h>
#include <math.h>
#include <stdint.h>

#define SIZE 1000
#define NPTS 8
#define THREADS 128
#define CHUNK 4                       // float4 stores per thread
#define BLK_F4 (THREADS * CHUNK)      // 512 float4s (8 KB) per block
#define N4 2500000                    // total float4s (10M floats / 4)
#define MAXCAND 400

// ---------------------------------------------------------------------------
// tanh(100000*x) with exact fp32 saturation fast path:
// tanhf(t) rounds to exactly +/-1.0f for |t| >= ~9.02, i.e. |x| >= 1e-4.
// ---------------------------------------------------------------------------
__device__ __forceinline__ float vi_sgn(float x) {
    if (fabsf(x) >= 1e-4f) return copysignf(1.0f, x);
    return tanhf(100000.0f * x);
}

// Exact mask element (pre-transpose i=row, j=col), faithful to the reference.
__device__ __forceinline__ float vi_maskval(float a, float b, int i, int j) {
    float x1 = vi_sgn(a - (float)j);
    float y1 = vi_sgn(b - (float)(i + 1));
    float x3 = vi_sgn(a - (float)(j + 1));
    float y3 = vi_sgn(b - (float)i);
    float m1 = vi_sgn(y1 * x1);
    float m3 = vi_sgn(y3 * x3);
    return (1.0f - m1 * m3) * 0.5f;
}

// Transposed mask with zero padding: mt(p,q) = mask(i=q, j=p)
__device__ __forceinline__ float vi_mt(float a, float b, int p, int q) {
    if (p < 0 || p >= SIZE || q < 0 || q >= SIZE) return 0.0f;
    return vi_maskval(a, b, q, p);
}

// ---------------------------------------------------------------------------
// Fused fill, barrier-free fast path. A/B vs R16: same 4883 blocks, same
// 8 KB footprint and store pattern, but 128 threads x CHUNK 4 -> HALF the
// warps, halving the fixed ~38-issue per-warp candidate overhead stream.
//   - 4 block-interleaved float4 zero stores per thread, issued first,
//     unpredicated (tail block wraps onto its own span; provably safe)
//   - every warp's lanes 0..7 compute the 8 closed-form candidate offsets
//     (single 1.0 at (jc*1000+ic)*10+cls per interior, saturated point)
//   - ballot: candidate in this block's span? almost always no -> done.
//     If yes, the thread that zero-stored that float4 applies atomicMax
//     (same-thread same-address ordering, no barrier needed).
//   - non-saturated inputs (near-integer band): block-uniform slow path
//     with exact 7x7 evaluation, shared list and __syncthreads.
// ---------------------------------------------------------------------------
__global__ void __launch_bounds__(THREADS) vi_fused_kernel(
        const float* __restrict__ z_pos,
        const int* __restrict__ z_cls,
        float4* __restrict__ out4) {
    __shared__ int   s_off[MAXCAND];
    __shared__ float s_val[MAXCAND];
    __shared__ int   s_cnt;

    int tid  = threadIdx.x;
    int lane = tid & 31;

    // early predicated input loads (every warp; broadcast addresses, L1-hit
    // after the first block on each SM)
    float a = 0.f, b = 0.f;
    int   c = 0;
    if (lane < NPTS) {
        float2 zp = ((const float2*)z_pos)[lane];
        a = zp.x * 1000.0f;
        b = zp.y * 1000.0f;
        c = z_cls[lane];
    }

    // 1. zero stores first — the bandwidth-bound bulk, no dependencies
    const float4 z = make_float4(0.f, 0.f, 0.f, 0.f);
    int blk_f4 = blockIdx.x * BLK_F4;
    {
        int i = blk_f4 + tid;
        #pragma unroll
        for (int u = 0; u < CHUNK; u++) {
            out4[min(i, N4 - 1)] = z;      // wrap-in-range for the tail block
            i += THREADS;
        }
    }

    // 2. closed-form candidate per lane (overlaps store drain)
    int  off = -1;
    bool sat = true;
    if (lane < NPTS) {
        int  jc = (int)floorf(a);
        int  ic = (int)floorf(b);
        float fa = a - (float)jc;
        float fb = b - (float)ic;
        sat = (fa >= 1e-4f) && (fa <= 1.0f - 1e-4f) &&
              (fb >= 1e-4f) && (fb <= 1.0f - 1e-4f);
        if (sat && jc >= 1 && jc <= SIZE - 2 && ic >= 1 && ic <= SIZE - 2)
            off = (jc * SIZE + ic) * 10 + c;
    }

    unsigned bad = __ballot_sync(0xffffffffu, (lane < NPTS) && !sat);

    if (bad == 0) {
        // 3. fast path: block-uniform, barrier-free
        int blk_lo = blk_f4 * 4;                  // first element of block
        bool inblk = (off >= blk_lo) && (off < blk_lo + BLK_F4 * 4);
        unsigned m = __ballot_sync(0xffffffffu, inblk);
        while (m) {
            int n = __ffs(m) - 1;
            m &= m - 1;
            int o = __shfl_sync(0xffffffffu, off, n);
            int r = (o >> 2) - blk_f4;            // float4 index within block
            if ((r & (THREADS - 1)) == tid) {     // I zero-stored this float4
                atomicMax((int*)((float*)out4 + o), __float_as_int(1.0f));
            }
        }
    } else {
        // 4. slow path (rare near-integer band): exact 7x7, shared list
        if (tid == 0) s_cnt = 0;
        __syncthreads();
        if (tid < NPTS) {
            int jc = (int)floorf(a);
            int ic = (int)floorf(b);
            for (int t = 0; t < 49; t++) {
                int p = jc + (t % 7) - 3;
                int q = ic + (t / 7) - 3;
                if (p < 0 || p >= SIZE || q < 0 || q >= SIZE) continue;
                float conv = vi_mt(a, b, p - 1, q) + vi_mt(a, b, p + 1, q) +
                             vi_mt(a, b, p, q - 1) + vi_mt(a, b, p, q + 1);
                float v = conv - 3.0f;
                if (v > 0.0f) {
                    int k = atomicAdd(&s_cnt, 1);
                    s_off[k] = (p * SIZE + q) * 10 + c;
                    s_val[k] = v;
                }
            }
        }
        __syncthreads();   // also makes all block zero-stores visible
        int cnt = s_cnt;
        int e_lo = blk_f4 * 4;
        for (int k = tid; k < cnt; k += THREADS) {
            unsigned d = (unsigned)(s_off[k] - e_lo);
            if (d < (unsigned)(BLK_F4 * 4))
                atomicMax((int*)((float*)out4 + s_off[k]),
                          __float_as_int(s_val[k]));
        }
    }
}

extern "C" void kernel_launch(void* const* d_in, const int* in_sizes, int n_in,
                              void* d_out, int out_size) {
    const float* z_pos = (const float*)d_in[0];  // [8,2] fp32
    const int*   z_cls = (const int*)d_in[1];    // [8] int32
    float* out = (float*)d_out;                  // [1000,1000,10] fp32
    (void)in_sizes; (void)n_in; (void)out_size;

    int blocks = (N4 + BLK_F4 - 1) / BLK_F4;     // 4883
    vi_fused_kernel<<<blocks, THREADS>>>(z_pos, z_cls, (float4*)out);
}